// round 3
// baseline (speedup 1.0000x reference)
#include <cuda_runtime.h>
#include <cstdint>

// DenseRoutingMaskLayer via TMA bulk-copy engine.
//   inputs:          [B=16384, D=4096] f32   (d_in[0])
//   routing_inputs:  [B=16384, R=8]    f32   (d_in[1])
//   out:             [B=16384, W=512]  f32
//
// Per CTA (128 thr): 16 rows. One coalesced load grabs 16x8 logits; 8-lane
// butterfly argmax (first-occurrence ties). Then per row ONE 2KB
// cp.async.bulk G->SMEM (gather), and per 8-row group ONE 16KB
// cp.async.bulk SMEM->G store (output of consecutive rows is contiguous).
// Deep MLP with zero register pressure; LSU path nearly idle.

constexpr int ROWS_PER_CTA  = 16;
constexpr int THREADS       = 128;
constexpr int ROW_BYTES     = 2048;                       // 512 f32
constexpr int GROUPS        = 2;
constexpr int ROWS_PER_GRP  = ROWS_PER_CTA / GROUPS;      // 8
constexpr int GROUP_BYTES   = ROWS_PER_GRP * ROW_BYTES;   // 16384
constexpr int BUF_BYTES     = ROWS_PER_CTA * ROW_BYTES;   // 32768
constexpr int SMEM_TOTAL    = BUF_BYTES + 128;            // + mbarriers/idx

__device__ __forceinline__ uint32_t smem_u32(const void* p) {
    return (uint32_t)__cvta_generic_to_shared(p);
}

__global__ __launch_bounds__(THREADS, 1)
void dense_routing_tma_kernel(const float* __restrict__ inputs,
                              const float* __restrict__ routing,
                              float* __restrict__ out,
                              int B) {
    extern __shared__ __align__(128) unsigned char smem[];
    unsigned char* buf = smem;                                          // 32KB
    unsigned long long* mbar = reinterpret_cast<unsigned long long*>(smem + BUF_BYTES);
    int* sidx = reinterpret_cast<int*>(smem + BUF_BYTES + 16);          // 16 ints

    const int tid  = threadIdx.x;
    const int row0 = blockIdx.x * ROWS_PER_CTA;
    if (row0 >= B) return;

    // init barriers (arrive count 1: the expect_tx arrival)
    if (tid < GROUPS) {
        uint32_t mb = smem_u32(&mbar[tid]);
        asm volatile("mbarrier.init.shared.b64 [%0], 1;" :: "r"(mb));
    }

    // ---- argmax: thread t holds routing[row0 + t/8][t%8] (one coalesced load)
    float v  = routing[(size_t)row0 * 8 + tid];
    int  idx = tid & 7;
    #pragma unroll
    for (int off = 1; off < 8; off <<= 1) {
        float v2 = __shfl_xor_sync(0xffffffffu, v,   off);
        int   i2 = __shfl_xor_sync(0xffffffffu, idx, off);
        // strict > keeps lower index on tie; on tie take smaller index
        if (v2 > v || (v2 == v && i2 < idx)) { v = v2; idx = i2; }
    }
    if ((tid & 7) == 0) sidx[tid >> 3] = idx;

    // set expected bytes before any load can complete
    if (tid < GROUPS) {
        uint32_t mb = smem_u32(&mbar[tid]);
        asm volatile("mbarrier.arrive.expect_tx.shared.b64 _, [%0], %1;"
                     :: "r"(mb), "r"(GROUP_BYTES) : "memory");
    }
    __syncthreads();   // orders init + sidx + expect_tx before TMA issues

    // ---- gather loads: one 2KB bulk copy per row, 16 in flight ----
    if (tid < ROWS_PER_CTA) {
        const int r = tid;
        uint32_t dst = smem_u32(buf + r * ROW_BYTES);
        uint32_t mb  = smem_u32(&mbar[r / ROWS_PER_GRP]);
        const void* src = inputs + (size_t)(row0 + r) * 4096 + (size_t)sidx[r] * 512;
        asm volatile(
            "cp.async.bulk.shared::cta.global.mbarrier::complete_tx::bytes "
            "[%0], [%1], %2, [%3];"
            :: "r"(dst), "l"(src), "r"(ROW_BYTES), "r"(mb) : "memory");
    }

    // ---- per group: wait arrival, fire one contiguous 16KB bulk store ----
    if (tid == 0) {
        #pragma unroll
        for (int g = 0; g < GROUPS; g++) {
            uint32_t mb = smem_u32(&mbar[g]);
            asm volatile(
                "{\n\t"
                ".reg .pred P;\n"
                "WAIT%=:\n\t"
                "mbarrier.try_wait.parity.shared.b64 P, [%0], 0, 10000000;\n\t"
                "@!P bra WAIT%=;\n\t"
                "}"
                :: "r"(mb) : "memory");
            uint32_t s = smem_u32(buf + g * GROUP_BYTES);
            void* dst = out + (size_t)row0 * 512 + (size_t)g * (GROUP_BYTES / 4);
            asm volatile(
                "cp.async.bulk.global.shared::cta.bulk_group [%0], [%1], %2;"
                :: "l"(dst), "r"(s), "r"(GROUP_BYTES) : "memory");
            asm volatile("cp.async.bulk.commit_group;" ::: "memory");
        }
        // smem must stay alive until stores have read it
        asm volatile("cp.async.bulk.wait_group 0;" ::: "memory");
    }
    __syncthreads();
}

extern "C" void kernel_launch(void* const* d_in, const int* in_sizes, int n_in,
                              void* d_out, int out_size) {
    const float* inputs  = (const float*)d_in[0];
    const float* routing = (const float*)d_in[1];
    float* out = (float*)d_out;

    const int B = in_sizes[1] / 8;                     // 16384
    const int blocks = (B + ROWS_PER_CTA - 1) / ROWS_PER_CTA;  // 1024

    cudaFuncSetAttribute(dense_routing_tma_kernel,
                         cudaFuncAttributeMaxDynamicSharedMemorySize, SMEM_TOTAL);
    dense_routing_tma_kernel<<<blocks, THREADS, SMEM_TOTAL>>>(inputs, routing, out, B);
}

// round 4
// speedup vs baseline: 1.1192x; 1.1192x over previous
#include <cuda_runtime.h>
#include <cstdint>

// DenseRoutingMaskLayer: per-row argmax over 8 routing logits selects a
// contiguous 512-float chunk of the 4096-wide input row.
//   inputs:          [B=16384, D=4096] f32   (d_in[0])
//   routing_inputs:  [B=16384, R=8]    f32   (d_in[1])
//   out:             [B=16384, W=512]  f32
//
// Round 4: R1 structure + 2 rows/warp + ballot-based argmax.
//  - lanes 0..15 load routing for 2 rows in one coalesced 64B access
//  - argmax per 8-lane group: 3x shfl_xor max + ballot + ffs
//    (lowest set bit == first occurrence, matching jnp.argmax ties)
//  - 8 independent LDG.128 in flight before any STG.128 (MLP 8/warp)
//  - ~44 regs -> ~60% occupancy (avoids R2's register cliff)

constexpr int ROWS_PER_WARP  = 2;
constexpr int WARPS_PER_CTA  = 8;
constexpr int ROWS_PER_CTA   = ROWS_PER_WARP * WARPS_PER_CTA;  // 16

__global__ __launch_bounds__(256, 5)
void dense_routing_mask_kernel(const float* __restrict__ inputs,
                               const float* __restrict__ routing,
                               float* __restrict__ out,
                               int B) {
    const int warp = threadIdx.x >> 5;
    const int lane = threadIdx.x & 31;
    const int row0 = blockIdx.x * ROWS_PER_CTA + warp * ROWS_PER_WARP;
    if (row0 >= B) return;

    // ---- routing: 2 rows x 8 logits, lanes 0..15, one coalesced load ----
    const float NEG_INF = -__int_as_float(0x7f800000);
    float v = (lane < 16) ? routing[(size_t)row0 * 8 + lane] : NEG_INF;

    // max within each 8-lane group
    float m = v;
    #pragma unroll
    for (int off = 1; off < 8; off <<= 1)
        m = fmaxf(m, __shfl_xor_sync(0xffffffffu, m, off));

    // first-occurrence argmax via ballot (all lanes see the full mask)
    const unsigned b = __ballot_sync(0xffffffffu, v == m);
    const int idx0 = __ffs(b & 0xFFu) - 1;          // row0
    const int idx1 = __ffs((b >> 8) & 0xFFu) - 1;   // row0 + 1

    // ---- copy: 2 rows x 4 float4 per lane; all loads before any store ----
    const float4* __restrict__ s0 = reinterpret_cast<const float4*>(
        inputs + (size_t)row0 * 4096 + (size_t)idx0 * 512);
    const float4* __restrict__ s1 = reinterpret_cast<const float4*>(
        inputs + (size_t)(row0 + 1) * 4096 + (size_t)idx1 * 512);
    float4* __restrict__ d0 = reinterpret_cast<float4*>(out + (size_t)row0 * 512);
    float4* __restrict__ d1 = reinterpret_cast<float4*>(out + (size_t)(row0 + 1) * 512);

    float4 b0[4], b1[4];
    #pragma unroll
    for (int i = 0; i < 4; i++) b0[i] = s0[lane + i * 32];
    #pragma unroll
    for (int i = 0; i < 4; i++) b1[i] = s1[lane + i * 32];

    #pragma unroll
    for (int i = 0; i < 4; i++) d0[lane + i * 32] = b0[i];
    #pragma unroll
    for (int i = 0; i < 4; i++) d1[lane + i * 32] = b1[i];
}

extern "C" void kernel_launch(void* const* d_in, const int* in_sizes, int n_in,
                              void* d_out, int out_size) {
    const float* inputs  = (const float*)d_in[0];
    const float* routing = (const float*)d_in[1];
    float* out = (float*)d_out;

    const int B = in_sizes[1] / 8;                               // 16384
    const int blocks = (B + ROWS_PER_CTA - 1) / ROWS_PER_CTA;    // 1024

    dense_routing_mask_kernel<<<blocks, 256>>>(inputs, routing, out, B);
}